// round 8
// baseline (speedup 1.0000x reference)
#include <cuda_runtime.h>
#include <cstdint>

#define S_DIM 8192
#define E_DIM 512
#define B_DIM 8
#define SE_DIM (S_DIM * E_DIM)
#define M_TOTAL 65536
#define K_DIM 512
#define N_DIM 512

#if defined(__CUDA_ARCH_FEAT_SM103_ALL) || defined(__CUDA_ARCH_FEAT_SM100_ALL) || \
    defined(__CUDA_ARCH_FEAT_SM101_ALL) || defined(__CUDA_ARCH_FEAT_SM110_ALL)
#define HAS_TCGEN05 1
#else
#define HAS_TCGEN05 0
#endif

// W scratch, CHUNK-MAJOR + PRE-SWIZZLED:
//   g_W32 byte (c*65536 + sw128(n*128 + j*4)) = tf32(W[n][c*32 + j])
__device__ float g_W32[(size_t)N_DIM * K_DIM];

// ---------------------------------------------------------------------------
__device__ __forceinline__ float to_tf32(float v) {
    float r;
    asm("cvt.rna.tf32.f32 %0, %1;" : "=f"(r) : "f"(v));
    return r;
}

__device__ __forceinline__ float fast_cos(float t) {
    float q = rintf(t * 0.63661977236758134f);
    int iq = (int)q;
    float r = fmaf(q, -1.57079637050628662109375f, t);
    r = fmaf(q, 4.37113900018624283e-8f, r);
    float z = r * r;
    float sp = fmaf(z, -1.9515295891e-4f, 8.3321608736e-3f);
    sp = fmaf(z, sp, -1.6666654611e-1f);
    float sinr = fmaf(r * z, sp, r);
    float cp = fmaf(z, 2.443315711809948e-5f, -1.388731625493765e-3f);
    cp = fmaf(z, cp, 4.166664568298827e-2f);
    cp = fmaf(z, cp, -0.5f);
    float cosr = fmaf(z, cp, 1.0f);
    float res = (iq & 1) ? sinr : cosr;
    if ((iq + 1) & 2) res = -res;
    return res;
}

__device__ __forceinline__ uint32_t smem_u32(const void* p) {
    uint32_t a;
    asm("{ .reg .u64 t; cvta.to.shared.u64 t, %1; cvt.u32.u64 %0, t; }" : "=r"(a) : "l"(p));
    return a;
}

#define MBAR_INIT(addr, cnt) \
    asm volatile("mbarrier.init.shared.b64 [%0], %1;" :: "r"(addr), "r"(cnt) : "memory")

#define MBAR_WAIT(addr, par) do {                                               \
    uint32_t _m = (addr); uint32_t _p = (par); uint32_t _d;                     \
    asm volatile("{\n\t.reg .pred p;\n\t"                                       \
        "mbarrier.try_wait.parity.acquire.cta.shared::cta.b64 p, [%1], %2;\n\t" \
        "selp.b32 %0, 1, 0, p;\n\t}"                                            \
        : "=r"(_d) : "r"(_m), "r"(_p) : "memory");                              \
    if (!_d) {                                                                  \
        asm volatile("{\n\t.reg .pred P1;\n\t"                                  \
            "WL_%=:\n\t"                                                        \
            "mbarrier.try_wait.parity.acquire.cta.shared::cta.b64 P1, [%0], %1, 0x989680;\n\t" \
            "@P1 bra.uni WD_%=;\n\t"                                            \
            "bra.uni WL_%=;\n\t"                                                \
            "WD_%=:\n\t}" :: "r"(_m), "r"(_p) : "memory");                      \
    }                                                                           \
} while (0)

__device__ __forceinline__ uint64_t make_desc_sw128(uint32_t addr) {
    const uint64_t base = (uint64_t(2) << 61) | (uint64_t(1) << 46) |
                          (uint64_t(64) << 32) | (uint64_t(1) << 16);
    return base | ((uint64_t)(addr >> 4) & 0x3FFF);
}

#define STS128(addr, a0, a1, a2, a3) \
    asm volatile("st.shared.v4.b32 [%0], {%1, %2, %3, %4};" \
                 :: "r"(addr), "r"(a0), "r"(a1), "r"(a2), "r"(a3) : "memory")

#if HAS_TCGEN05
__device__ __forceinline__ void mma_tf32_ss(uint32_t d_tmem, uint64_t a_desc,
                                            uint64_t b_desc, uint32_t idesc,
                                            uint32_t enable) {
    asm volatile(
        "{\n\t.reg .pred p;\n\t"
        "setp.ne.u32 p, %4, 0;\n\t"
        "tcgen05.mma.cta_group::1.kind::tf32 [%0], %1, %2, %3, p;\n\t}"
        :: "r"(d_tmem), "l"(a_desc), "l"(b_desc), "r"(idesc), "r"(enable)
        : "memory");
}
#endif

// ---------------------------------------------------------------------------
// Stage 0: round W to tf32, chunk-major + pre-swizzled.
// ---------------------------------------------------------------------------
__global__ __launch_bounds__(256) void roundw_kernel(const float* __restrict__ W) {
    int tid = blockIdx.x * 256 + threadIdx.x;
    int n    = tid >> 7;
    int rest = tid & 127;
    int c    = rest >> 3;
    int seg  = rest & 7;

    float4 v = *(const float4*)(W + (size_t)n * K_DIM + c * 32 + seg * 4);
    v.x = to_tf32(v.x); v.y = to_tf32(v.y); v.z = to_tf32(v.z); v.w = to_tf32(v.w);

    uint32_t byte_off = (uint32_t)n * 128 + seg * 16;
    uint32_t sw = byte_off ^ ((byte_off >> 3) & 0x70);
    *(float4*)((char*)g_W32 + (size_t)c * 65536 + sw) = v;
}

// ---------------------------------------------------------------------------
// Fused kernel: one CTA = 128-row x 512-col tile. Decoupled pipeline:
//   warps 0-7 : x prefetch (1 chunk ahead, regs) + cos + A STS + epilogue
//   warp 8    : MMA issue; per chunk 2 commits (doneA ring, doneB ring)
//   warp 9    : B bulk-copy producer, NS_B = 3 stages
// ---------------------------------------------------------------------------
#define NCHUNK 16
#define NSA 2
#define NSB 3
#define SMEM_A0 1024
#define A_STAGE 16384                         // 128 rows x 128B
#define SMEM_B0 (SMEM_A0 + NSA * A_STAGE)     // 33792
#define B_STAGE 65536                         // 512 rows x 128B
#define FUSED_SMEM (SMEM_B0 + NSB * B_STAGE)  // 230400

// control block offsets
#define OFF_FULLA 16      // 2 x 8B
#define OFF_DONEA 32      // 2 x 8B
#define OFF_FULLB 48      // 3 x 8B
#define OFF_DONEB 72      // 3 x 8B

static constexpr uint32_t IDESC_N256 =
    (1u << 4)                // D = F32
    | (2u << 7)              // A = TF32
    | (2u << 10)             // B = TF32
    | ((256u / 8u) << 17)    // N = 256
    | ((128u / 16u) << 24);  // M = 128

extern "C" __global__ void __launch_bounds__(320, 1)
fused_kernel(const float* __restrict__ x, const float* __restrict__ theta,
             float* __restrict__ C) {
#if HAS_TCGEN05
    extern __shared__ char smem[];
    uint32_t smem_base = smem_u32(smem);
    int tid = threadIdx.x;
    int wid = tid >> 5;
    int lid = tid & 31;

    int t = blockIdx.x;
    int b = t >> 6;
    int h = t & 63;
    int m0 = t << 7;

    uint32_t fullA = smem_base + OFF_FULLA;
    uint32_t doneA = smem_base + OFF_DONEA;
    uint32_t fullB = smem_base + OFF_FULLB;
    uint32_t doneB = smem_base + OFF_DONEB;

    if (tid == 0) {
        for (int s = 0; s < NSA; s++) {
            MBAR_INIT(fullA + 8 * s, 256);   // 256 worker threads
            MBAR_INIT(doneA + 8 * s, 1);
        }
        for (int s = 0; s < NSB; s++) {
            MBAR_INIT(fullB + 8 * s, 1);     // expect_tx arrive
            MBAR_INIT(doneB + 8 * s, 1);
        }
    }
    if (wid == 8) {
        asm volatile("tcgen05.alloc.cta_group::1.sync.aligned.shared::cta.b32 [%0], %1;"
                     :: "r"(smem_base), "r"(512u) : "memory");
        asm volatile("tcgen05.relinquish_alloc_permit.cta_group::1.sync.aligned;");
    }
    __syncthreads();
    uint32_t tmem;
    asm volatile("ld.shared.b32 %0, [%1];" : "=r"(tmem) : "r"(smem_base));

    if (wid < 8) {
        // ================= worker warps (256 threads) =================
        int r = tid >> 1;
        int half = tid & 1;
        const float* xs = x + ((size_t)b << 22) + (size_t)h * 8;
        float th0 = __ldg(theta + 0), th1 = __ldg(theta + 1);
        float th2 = __ldg(theta + 2), th3 = __ldg(theta + 3);
        float th4 = __ldg(theta + 4), th5 = __ldg(theta + 5);
        float th6 = __ldg(theta + 6), th7 = __ldg(theta + 7);
        int xa = (r & 7) * 16;
        uint32_t arow = smem_base + SMEM_A0 + r * 128;

        // prefetch chunk 0
        float4 p0, p1, p2, p3;
        {
            const float* xp = xs + (size_t)(r * 64 + half * 2) * E_DIM;
            p0 = *(const float4*)(xp);
            p1 = *(const float4*)(xp + 4);
            p2 = *(const float4*)(xp + E_DIM);
            p3 = *(const float4*)(xp + E_DIM + 4);
        }

        for (int i = 0; i < NCHUNK; i++) {
            // ---- prefetch chunk i+1 (issued before any waiting) ----
            float4 n0, n1, n2, n3;
            if (i < NCHUNK - 1) {
                const float* xp = xs + (size_t)(r * 64 + (i + 1) * 4 + half * 2) * E_DIM;
                n0 = *(const float4*)(xp);
                n1 = *(const float4*)(xp + 4);
                n2 = *(const float4*)(xp + E_DIM);
                n3 = *(const float4*)(xp + E_DIM + 4);
            }

            int st = i & 1;
            if (i >= NSA) MBAR_WAIT(doneA + 8 * st, ((i - NSA) >> 1) & 1);

            uint32_t v[16];
            v[0]  = __float_as_uint(to_tf32(fast_cos(p0.x + th0)));
            v[1]  = __float_as_uint(to_tf32(fast_cos(p0.y + th1)));
            v[2]  = __float_as_uint(to_tf32(fast_cos(p0.z + th2)));
            v[3]  = __float_as_uint(to_tf32(fast_cos(p0.w + th3)));
            v[4]  = __float_as_uint(to_tf32(fast_cos(p1.x + th4)));
            v[5]  = __float_as_uint(to_tf32(fast_cos(p1.y + th5)));
            v[6]  = __float_as_uint(to_tf32(fast_cos(p1.z + th6)));
            v[7]  = __float_as_uint(to_tf32(fast_cos(p1.w + th7)));
            v[8]  = __float_as_uint(to_tf32(fast_cos(p2.x + th0)));
            v[9]  = __float_as_uint(to_tf32(fast_cos(p2.y + th1)));
            v[10] = __float_as_uint(to_tf32(fast_cos(p2.z + th2)));
            v[11] = __float_as_uint(to_tf32(fast_cos(p2.w + th3)));
            v[12] = __float_as_uint(to_tf32(fast_cos(p3.x + th4)));
            v[13] = __float_as_uint(to_tf32(fast_cos(p3.y + th5)));
            v[14] = __float_as_uint(to_tf32(fast_cos(p3.z + th6)));
            v[15] = __float_as_uint(to_tf32(fast_cos(p3.w + th7)));

            uint32_t ad = arow + st * A_STAGE;
            STS128(ad + ((half * 64 + 0)  ^ xa), v[0],  v[1],  v[2],  v[3]);
            STS128(ad + ((half * 64 + 16) ^ xa), v[4],  v[5],  v[6],  v[7]);
            STS128(ad + ((half * 64 + 32) ^ xa), v[8],  v[9],  v[10], v[11]);
            STS128(ad + ((half * 64 + 48) ^ xa), v[12], v[13], v[14], v[15]);

            asm volatile("fence.proxy.async.shared::cta;" ::: "memory");
            asm volatile("mbarrier.arrive.shared.b64 _, [%0];"
                         :: "r"(fullA + 8 * st) : "memory");

            p0 = n0; p1 = n1; p2 = n2; p3 = n3;
        }

        // ================= epilogue =================
        // chunk 15 commits to doneA[1], fire index 7 -> parity 1.
        MBAR_WAIT(doneA + 8 * 1, 1);
        asm volatile("tcgen05.fence::after_thread_sync;" ::: "memory");

        int row = (wid & 3) * 32 + lid;
        int c0 = (wid >= 4) ? 256 : 0;
        float* Crow = C + (size_t)(m0 + row) * N_DIM + c0;
#pragma unroll
        for (int c = 0; c < 8; c++) {
            uint32_t d[32];
            asm volatile(
                "tcgen05.ld.sync.aligned.32x32b.x32.b32 "
                "{%0, %1, %2, %3, %4, %5, %6, %7, "
                " %8, %9, %10, %11, %12, %13, %14, %15, "
                " %16, %17, %18, %19, %20, %21, %22, %23, "
                " %24, %25, %26, %27, %28, %29, %30, %31}, [%32];"
                : "=r"(d[0]), "=r"(d[1]), "=r"(d[2]), "=r"(d[3]),
                  "=r"(d[4]), "=r"(d[5]), "=r"(d[6]), "=r"(d[7]),
                  "=r"(d[8]), "=r"(d[9]), "=r"(d[10]), "=r"(d[11]),
                  "=r"(d[12]), "=r"(d[13]), "=r"(d[14]), "=r"(d[15]),
                  "=r"(d[16]), "=r"(d[17]), "=r"(d[18]), "=r"(d[19]),
                  "=r"(d[20]), "=r"(d[21]), "=r"(d[22]), "=r"(d[23]),
                  "=r"(d[24]), "=r"(d[25]), "=r"(d[26]), "=r"(d[27]),
                  "=r"(d[28]), "=r"(d[29]), "=r"(d[30]), "=r"(d[31])
                : "r"(tmem + c0 + 32 * c));
            asm volatile("tcgen05.wait::ld.sync.aligned;" ::: "memory");
#pragma unroll
            for (int j = 0; j < 8; j++) {
                float4 o = make_float4(__uint_as_float(d[4 * j + 0]),
                                       __uint_as_float(d[4 * j + 1]),
                                       __uint_as_float(d[4 * j + 2]),
                                       __uint_as_float(d[4 * j + 3]));
                *(float4*)(Crow + 32 * c + 4 * j) = o;
            }
        }
        asm volatile("tcgen05.fence::before_thread_sync;" ::: "memory");
    } else if (wid == 8) {
        // ================= MMA warp =================
#pragma unroll
        for (int i = 0; i < NCHUNK; i++) {
            int stA = i & 1;
            int stB = i % 3;
            MBAR_WAIT(fullA + 8 * stA, (i >> 1) & 1);
            MBAR_WAIT(fullB + 8 * stB, (i / 3) & 1);
            asm volatile("fence.proxy.async.shared::cta;" ::: "memory");
            if (lid == 0) {
                uint32_t ab = smem_base + SMEM_A0 + stA * A_STAGE;
                uint32_t bb = smem_base + SMEM_B0 + stB * B_STAGE;
                uint64_t ad  = make_desc_sw128(ab);
                uint64_t bd0 = make_desc_sw128(bb);
                uint64_t bd1 = make_desc_sw128(bb + 256 * 128);
#pragma unroll
                for (int k = 0; k < 4; k++) {
                    uint32_t en = (i | k) != 0;
                    mma_tf32_ss(tmem,       ad + 2 * k, bd0 + 2 * k, IDESC_N256, en);
                    mma_tf32_ss(tmem + 256, ad + 2 * k, bd1 + 2 * k, IDESC_N256, en);
                }
                asm volatile(
                    "tcgen05.commit.cta_group::1.mbarrier::arrive::one.shared::cluster.b64 [%0];"
                    :: "r"(doneA + 8 * stA) : "memory");
                asm volatile(
                    "tcgen05.commit.cta_group::1.mbarrier::arrive::one.shared::cluster.b64 [%0];"
                    :: "r"(doneB + 8 * stB) : "memory");
            }
        }
    } else {
        // ================= B producer warp (wid == 9) =================
#pragma unroll
        for (int i = 0; i < NCHUNK; i++) {
            int stB = i % 3;
            if (i >= NSB) MBAR_WAIT(doneB + 8 * stB, ((i - NSB) / 3) & 1);
            if (lid == 0) {
                uint32_t bar = fullB + 8 * stB;
                asm volatile("mbarrier.arrive.expect_tx.shared::cta.b64 _, [%0], %1;"
                             :: "r"(bar), "r"((uint32_t)B_STAGE) : "memory");
                const char* src = (const char*)g_W32 + (size_t)i * B_STAGE;
                uint32_t dst = smem_base + SMEM_B0 + stB * B_STAGE;
                asm volatile(
                    "cp.async.bulk.shared::cta.global.mbarrier::complete_tx::bytes "
                    "[%0], [%1], %2, [%3];"
                    :: "r"(dst), "l"(src), "r"((uint32_t)B_STAGE), "r"(bar)
                    : "memory");
            }
        }
    }

    __syncthreads();
    if (wid == 8) {
        asm volatile("tcgen05.dealloc.cta_group::1.sync.aligned.b32 %0, %1;"
                     :: "r"(tmem), "r"(512u));
    }
#else
    // Correct SIMT fallback for the non-arch-specific cubin (never selected
    // on GB300). Reads the chunk-major pre-swizzled g_W32 layout.
    int g = blockIdx.x;
    int b = g >> 6;
    int h = g & 63;
    int m0 = g << 7;
    for (int idx = threadIdx.x; idx < 128 * N_DIM; idx += 320) {
        int r = idx >> 9, n = idx & 511;
        float acc = 0.0f;
        for (int k = 0; k < K_DIM; k++) {
            int s = r * 64 + (k >> 3);
            int wire = k & 7;
            float a = fast_cos(x[(size_t)b * SE_DIM + (size_t)s * E_DIM + h * 8 + wire]
                               + theta[wire]);
            int c = k >> 5, kk = k & 31;
            uint32_t byte_off = (uint32_t)n * 128 + kk * 4;
            uint32_t sw = byte_off ^ ((byte_off >> 3) & 0x70);
            float w = *(const float*)((const char*)g_W32 + (size_t)c * 65536 + sw);
            acc = fmaf(to_tf32(a), w, acc);
        }
        C[(size_t)(m0 + r) * N_DIM + n] = acc;
    }
#endif
}

// ---------------------------------------------------------------------------
extern "C" void kernel_launch(void* const* d_in, const int* in_sizes, int n_in,
                              void* d_out, int out_size) {
    const float* x     = (const float*)d_in[0];
    const float* theta = (const float*)d_in[1];
    const float* W     = (const float*)d_in[2];
    float* y = (float*)d_out;

    static bool attr_done = false;
    if (!attr_done) {
        cudaFuncSetAttribute(fused_kernel,
                             cudaFuncAttributeMaxDynamicSharedMemorySize, FUSED_SMEM);
        attr_done = true;
    }

    roundw_kernel<<<256, 256>>>(W);
    fused_kernel<<<512, 320, FUSED_SMEM>>>(x, theta, y);
}

// round 9
// speedup vs baseline: 1.1971x; 1.1971x over previous
#include <cuda_runtime.h>
#include <cstdint>

#define S_DIM 8192
#define E_DIM 512
#define B_DIM 8
#define SE_DIM (S_DIM * E_DIM)
#define M_TOTAL 65536
#define K_DIM 512
#define N_DIM 512

#if defined(__CUDA_ARCH_FEAT_SM103_ALL) || defined(__CUDA_ARCH_FEAT_SM100_ALL) || \
    defined(__CUDA_ARCH_FEAT_SM101_ALL) || defined(__CUDA_ARCH_FEAT_SM110_ALL)
#define HAS_TCGEN05 1
#else
#define HAS_TCGEN05 0
#endif

// W scratch, CHUNK-MAJOR + PRE-SWIZZLED:
//   g_W32 byte (c*65536 + sw128(n*128 + j*4)) = tf32(W[n][c*32 + j])
__device__ float g_W32[(size_t)N_DIM * K_DIM];

// ---------------------------------------------------------------------------
__device__ __forceinline__ float to_tf32(float v) {
    float r;
    asm("cvt.rna.tf32.f32 %0, %1;" : "=f"(r) : "f"(v));
    return r;
}

// XU-free cos + tf32 rounding: only fma/alu-pipe ops (no FRND/F2I/CVT).
// Valid for |t| < ~1e5 (inputs here are |x+theta| < ~12).
__device__ __forceinline__ uint32_t cos_tf32_bits(float t) {
    const float MAGIC = 12582912.0f;               // 1.5 * 2^23
    float g = fmaf(t, 0.63661977236758134f, MAGIC);
    int q = __float_as_int(g);                     // low bits = round(t*2/pi) mod 2^22
    float qf = g - MAGIC;                          // = rint(t*2/pi), exact
    float r = fmaf(qf, -1.57079637050628662109375f, t);
    r = fmaf(qf, 4.37113900018624283e-8f, r);
    float z = r * r;
    float sp = fmaf(z, -1.9515295891e-4f, 8.3321608736e-3f);
    sp = fmaf(z, sp, -1.6666654611e-1f);
    float sinr = fmaf(r * z, sp, r);
    float cp = fmaf(z, 2.443315711809948e-5f, -1.388731625493765e-3f);
    cp = fmaf(z, cp, 4.166664568298827e-2f);
    cp = fmaf(z, cp, -0.5f);
    float cosr = fmaf(z, cp, 1.0f);
    uint32_t res = (q & 1) ? __float_as_uint(sinr) : __float_as_uint(cosr);
    res ^= (uint32_t)((q + 1) & 2) << 30;          // negate if ((q+1)&2)
    res = (res + 0x1000u) & 0xFFFFE000u;           // tf32 round-to-nearest (ties away)
    return res;
}

__device__ __forceinline__ uint32_t smem_u32(const void* p) {
    uint32_t a;
    asm("{ .reg .u64 t; cvta.to.shared.u64 t, %1; cvt.u32.u64 %0, t; }" : "=r"(a) : "l"(p));
    return a;
}

#define MBAR_INIT(addr, cnt) \
    asm volatile("mbarrier.init.shared.b64 [%0], %1;" :: "r"(addr), "r"(cnt) : "memory")

#define MBAR_WAIT(addr, par) do {                                               \
    uint32_t _m = (addr); uint32_t _p = (par); uint32_t _d;                     \
    asm volatile("{\n\t.reg .pred p;\n\t"                                       \
        "mbarrier.try_wait.parity.acquire.cta.shared::cta.b64 p, [%1], %2;\n\t" \
        "selp.b32 %0, 1, 0, p;\n\t}"                                            \
        : "=r"(_d) : "r"(_m), "r"(_p) : "memory");                              \
    if (!_d) {                                                                  \
        asm volatile("{\n\t.reg .pred P1;\n\t"                                  \
            "WL_%=:\n\t"                                                        \
            "mbarrier.try_wait.parity.acquire.cta.shared::cta.b64 P1, [%0], %1, 0x989680;\n\t" \
            "@P1 bra.uni WD_%=;\n\t"                                            \
            "bra.uni WL_%=;\n\t"                                                \
            "WD_%=:\n\t}" :: "r"(_m), "r"(_p) : "memory");                      \
    }                                                                           \
} while (0)

__device__ __forceinline__ uint64_t make_desc_sw128(uint32_t addr) {
    const uint64_t base = (uint64_t(2) << 61) | (uint64_t(1) << 46) |
                          (uint64_t(64) << 32) | (uint64_t(1) << 16);
    return base | ((uint64_t)(addr >> 4) & 0x3FFF);
}

#define STS128(addr, a0, a1, a2, a3) \
    asm volatile("st.shared.v4.b32 [%0], {%1, %2, %3, %4};" \
                 :: "r"(addr), "r"(a0), "r"(a1), "r"(a2), "r"(a3) : "memory")

#if HAS_TCGEN05
__device__ __forceinline__ void mma_tf32_ss(uint32_t d_tmem, uint64_t a_desc,
                                            uint64_t b_desc, uint32_t idesc,
                                            uint32_t enable) {
    asm volatile(
        "{\n\t.reg .pred p;\n\t"
        "setp.ne.u32 p, %4, 0;\n\t"
        "tcgen05.mma.cta_group::1.kind::tf32 [%0], %1, %2, %3, p;\n\t}"
        :: "r"(d_tmem), "l"(a_desc), "l"(b_desc), "r"(idesc), "r"(enable)
        : "memory");
}
#endif

// ---------------------------------------------------------------------------
// Stage 0: round W to tf32, chunk-major + pre-swizzled.
// ---------------------------------------------------------------------------
__global__ __launch_bounds__(256) void roundw_kernel(const float* __restrict__ W) {
    int tid = blockIdx.x * 256 + threadIdx.x;
    int n    = tid >> 7;
    int rest = tid & 127;
    int c    = rest >> 3;
    int seg  = rest & 7;

    float4 v = *(const float4*)(W + (size_t)n * K_DIM + c * 32 + seg * 4);
    v.x = to_tf32(v.x); v.y = to_tf32(v.y); v.z = to_tf32(v.z); v.w = to_tf32(v.w);

    uint32_t byte_off = (uint32_t)n * 128 + seg * 16;
    uint32_t sw = byte_off ^ ((byte_off >> 3) & 0x70);
    *(float4*)((char*)g_W32 + (size_t)c * 65536 + sw) = v;
}

// ---------------------------------------------------------------------------
// Fused kernel: one CTA = 128-row x 512-col tile.
//   warps 0-7 : x load + cos + A STS (4-stage ring) + epilogue
//   warp 8    : MMA issue, commits doneA + doneB per chunk
//   warp 9    : B bulk-copy producer (2-stage ring)
// ---------------------------------------------------------------------------
#define NCHUNK 16
#define NSA 4
#define NSB 2
#define SMEM_A0 1024
#define A_STAGE 16384                         // 128 rows x 128B
#define SMEM_B0 (SMEM_A0 + NSA * A_STAGE)     // 66560
#define B_STAGE 65536                         // 512 rows x 128B
#define FUSED_SMEM (SMEM_B0 + NSB * B_STAGE)  // 197632

// control block offsets
#define OFF_FULLA 16      // 4 x 8B
#define OFF_DONEA 48      // 4 x 8B
#define OFF_FULLB 80      // 2 x 8B
#define OFF_DONEB 96      // 2 x 8B

static constexpr uint32_t IDESC_N256 =
    (1u << 4)                // D = F32
    | (2u << 7)              // A = TF32
    | (2u << 10)             // B = TF32
    | ((256u / 8u) << 17)    // N = 256
    | ((128u / 16u) << 24);  // M = 128

extern "C" __global__ void __launch_bounds__(320, 1)
fused_kernel(const float* __restrict__ x, const float* __restrict__ theta,
             float* __restrict__ C) {
#if HAS_TCGEN05
    extern __shared__ char smem[];
    uint32_t smem_base = smem_u32(smem);
    int tid = threadIdx.x;
    int wid = tid >> 5;
    int lid = tid & 31;

    int t = blockIdx.x;
    int b = t >> 6;
    int h = t & 63;
    int m0 = t << 7;

    uint32_t fullA = smem_base + OFF_FULLA;
    uint32_t doneA = smem_base + OFF_DONEA;
    uint32_t fullB = smem_base + OFF_FULLB;
    uint32_t doneB = smem_base + OFF_DONEB;

    if (tid == 0) {
        for (int s = 0; s < NSA; s++) {
            MBAR_INIT(fullA + 8 * s, 8);     // one arrive per worker warp
            MBAR_INIT(doneA + 8 * s, 1);
        }
        for (int s = 0; s < NSB; s++) {
            MBAR_INIT(fullB + 8 * s, 1);     // expect_tx arrive
            MBAR_INIT(doneB + 8 * s, 1);
        }
    }
    if (wid == 8) {
        asm volatile("tcgen05.alloc.cta_group::1.sync.aligned.shared::cta.b32 [%0], %1;"
                     :: "r"(smem_base), "r"(512u) : "memory");
        asm volatile("tcgen05.relinquish_alloc_permit.cta_group::1.sync.aligned;");
    }
    __syncthreads();
    uint32_t tmem;
    asm volatile("ld.shared.b32 %0, [%1];" : "=r"(tmem) : "r"(smem_base));

    if (wid < 8) {
        // ================= worker warps (256 threads) =================
        int r = tid >> 1;
        int half = tid & 1;
        const float* xs = x + ((size_t)b << 22) + (size_t)h * 8;
        float th0 = __ldg(theta + 0), th1 = __ldg(theta + 1);
        float th2 = __ldg(theta + 2), th3 = __ldg(theta + 3);
        float th4 = __ldg(theta + 4), th5 = __ldg(theta + 5);
        float th6 = __ldg(theta + 6), th7 = __ldg(theta + 7);
        int xa = (r & 7) * 16;
        uint32_t arow = smem_base + SMEM_A0 + r * 128;

        for (int i = 0; i < NCHUNK; i++) {
            // issue x loads for this chunk BEFORE the ring wait (latency overlap)
            int sb = r * 64 + i * 4 + half * 2;
            const float* xp = xs + (size_t)sb * E_DIM;
            float4 x0 = *(const float4*)(xp);
            float4 x1 = *(const float4*)(xp + 4);
            float4 x2 = *(const float4*)(xp + E_DIM);
            float4 x3 = *(const float4*)(xp + E_DIM + 4);

            int st = i & 3;
            if (i >= NSA) MBAR_WAIT(doneA + 8 * st, ((i - NSA) >> 2) & 1);

            uint32_t v[16];
            v[0]  = cos_tf32_bits(x0.x + th0);
            v[1]  = cos_tf32_bits(x0.y + th1);
            v[2]  = cos_tf32_bits(x0.z + th2);
            v[3]  = cos_tf32_bits(x0.w + th3);
            v[4]  = cos_tf32_bits(x1.x + th4);
            v[5]  = cos_tf32_bits(x1.y + th5);
            v[6]  = cos_tf32_bits(x1.z + th6);
            v[7]  = cos_tf32_bits(x1.w + th7);
            v[8]  = cos_tf32_bits(x2.x + th0);
            v[9]  = cos_tf32_bits(x2.y + th1);
            v[10] = cos_tf32_bits(x2.z + th2);
            v[11] = cos_tf32_bits(x2.w + th3);
            v[12] = cos_tf32_bits(x3.x + th4);
            v[13] = cos_tf32_bits(x3.y + th5);
            v[14] = cos_tf32_bits(x3.z + th6);
            v[15] = cos_tf32_bits(x3.w + th7);

            uint32_t ad = arow + st * A_STAGE;
            STS128(ad + ((half * 64 + 0)  ^ xa), v[0],  v[1],  v[2],  v[3]);
            STS128(ad + ((half * 64 + 16) ^ xa), v[4],  v[5],  v[6],  v[7]);
            STS128(ad + ((half * 64 + 32) ^ xa), v[8],  v[9],  v[10], v[11]);
            STS128(ad + ((half * 64 + 48) ^ xa), v[12], v[13], v[14], v[15]);

            asm volatile("fence.proxy.async.shared::cta;" ::: "memory");
            __syncwarp();
            if (lid == 0)
                asm volatile("mbarrier.arrive.shared.b64 _, [%0];"
                             :: "r"(fullA + 8 * st) : "memory");
        }

        // ================= epilogue =================
        // chunk 15 commits doneA stage 3 (4th fire -> parity 1)
        MBAR_WAIT(doneA + 8 * 3, 1);
        asm volatile("tcgen05.fence::after_thread_sync;" ::: "memory");

        int row = (wid & 3) * 32 + lid;
        int c0 = (wid >= 4) ? 256 : 0;
        float* Crow = C + (size_t)(m0 + row) * N_DIM + c0;
#pragma unroll
        for (int c = 0; c < 8; c++) {
            uint32_t d[32];
            asm volatile(
                "tcgen05.ld.sync.aligned.32x32b.x32.b32 "
                "{%0, %1, %2, %3, %4, %5, %6, %7, "
                " %8, %9, %10, %11, %12, %13, %14, %15, "
                " %16, %17, %18, %19, %20, %21, %22, %23, "
                " %24, %25, %26, %27, %28, %29, %30, %31}, [%32];"
                : "=r"(d[0]), "=r"(d[1]), "=r"(d[2]), "=r"(d[3]),
                  "=r"(d[4]), "=r"(d[5]), "=r"(d[6]), "=r"(d[7]),
                  "=r"(d[8]), "=r"(d[9]), "=r"(d[10]), "=r"(d[11]),
                  "=r"(d[12]), "=r"(d[13]), "=r"(d[14]), "=r"(d[15]),
                  "=r"(d[16]), "=r"(d[17]), "=r"(d[18]), "=r"(d[19]),
                  "=r"(d[20]), "=r"(d[21]), "=r"(d[22]), "=r"(d[23]),
                  "=r"(d[24]), "=r"(d[25]), "=r"(d[26]), "=r"(d[27]),
                  "=r"(d[28]), "=r"(d[29]), "=r"(d[30]), "=r"(d[31])
                : "r"(tmem + c0 + 32 * c));
            asm volatile("tcgen05.wait::ld.sync.aligned;" ::: "memory");
#pragma unroll
            for (int j = 0; j < 8; j++) {
                float4 o = make_float4(__uint_as_float(d[4 * j + 0]),
                                       __uint_as_float(d[4 * j + 1]),
                                       __uint_as_float(d[4 * j + 2]),
                                       __uint_as_float(d[4 * j + 3]));
                *(float4*)(Crow + 32 * c + 4 * j) = o;
            }
        }
        asm volatile("tcgen05.fence::before_thread_sync;" ::: "memory");
    } else if (wid == 8) {
        // ================= MMA warp =================
        for (int i = 0; i < NCHUNK; i++) {
            int stA = i & 3;
            int stB = i & 1;
            MBAR_WAIT(fullA + 8 * stA, (i >> 2) & 1);
            MBAR_WAIT(fullB + 8 * stB, (i >> 1) & 1);
            asm volatile("fence.proxy.async.shared::cta;" ::: "memory");
            if (lid == 0) {
                uint32_t ab = smem_base + SMEM_A0 + stA * A_STAGE;
                uint32_t bb = smem_base + SMEM_B0 + stB * B_STAGE;
                uint64_t ad  = make_desc_sw128(ab);
                uint64_t bd0 = make_desc_sw128(bb);
                uint64_t bd1 = make_desc_sw128(bb + 256 * 128);
#pragma unroll
                for (int k = 0; k < 4; k++) {
                    uint32_t en = (i | k) != 0;
                    mma_tf32_ss(tmem,       ad + 2 * k, bd0 + 2 * k, IDESC_N256, en);
                    mma_tf32_ss(tmem + 256, ad + 2 * k, bd1 + 2 * k, IDESC_N256, en);
                }
                asm volatile(
                    "tcgen05.commit.cta_group::1.mbarrier::arrive::one.shared::cluster.b64 [%0];"
                    :: "r"(doneA + 8 * stA) : "memory");
                asm volatile(
                    "tcgen05.commit.cta_group::1.mbarrier::arrive::one.shared::cluster.b64 [%0];"
                    :: "r"(doneB + 8 * stB) : "memory");
            }
        }
    } else {
        // ================= B producer warp (wid == 9) =================
        for (int i = 0; i < NCHUNK; i++) {
            int stB = i & 1;
            if (i >= NSB) MBAR_WAIT(doneB + 8 * stB, ((i - NSB) >> 1) & 1);
            if (lid == 0) {
                uint32_t bar = fullB + 8 * stB;
                asm volatile("mbarrier.arrive.expect_tx.shared::cta.b64 _, [%0], %1;"
                             :: "r"(bar), "r"((uint32_t)B_STAGE) : "memory");
                const char* src = (const char*)g_W32 + (size_t)i * B_STAGE;
                uint32_t dst = smem_base + SMEM_B0 + stB * B_STAGE;
                asm volatile(
                    "cp.async.bulk.shared::cta.global.mbarrier::complete_tx::bytes "
                    "[%0], [%1], %2, [%3];"
                    :: "r"(dst), "l"(src), "r"((uint32_t)B_STAGE), "r"(bar)
                    : "memory");
            }
        }
    }

    __syncthreads();
    if (wid == 8) {
        asm volatile("tcgen05.dealloc.cta_group::1.sync.aligned.b32 %0, %1;"
                     :: "r"(tmem), "r"(512u));
    }
#else
    // Correct SIMT fallback for the non-arch-specific cubin (never selected
    // on GB300). Reads the chunk-major pre-swizzled g_W32 layout.
    int g = blockIdx.x;
    int b = g >> 6;
    int h = g & 63;
    int m0 = g << 7;
    for (int idx = threadIdx.x; idx < 128 * N_DIM; idx += 320) {
        int r = idx >> 9, n = idx & 511;
        float acc = 0.0f;
        for (int k = 0; k < K_DIM; k++) {
            int s = r * 64 + (k >> 3);
            int wire = k & 7;
            float a = __uint_as_float(cos_tf32_bits(
                x[(size_t)b * SE_DIM + (size_t)s * E_DIM + h * 8 + wire] + theta[wire]));
            int c = k >> 5, kk = k & 31;
            uint32_t byte_off = (uint32_t)n * 128 + kk * 4;
            uint32_t sw = byte_off ^ ((byte_off >> 3) & 0x70);
            float w = *(const float*)((const char*)g_W32 + (size_t)c * 65536 + sw);
            acc = fmaf(a, w, acc);
        }
        C[(size_t)(m0 + r) * N_DIM + n] = acc;
    }
#endif
}

// ---------------------------------------------------------------------------
extern "C" void kernel_launch(void* const* d_in, const int* in_sizes, int n_in,
                              void* d_out, int out_size) {
    const float* x     = (const float*)d_in[0];
    const float* theta = (const float*)d_in[1];
    const float* W     = (const float*)d_in[2];
    float* y = (float*)d_out;

    static bool attr_done = false;
    if (!attr_done) {
        cudaFuncSetAttribute(fused_kernel,
                             cudaFuncAttributeMaxDynamicSharedMemorySize, FUSED_SMEM);
        attr_done = true;
    }

    roundw_kernel<<<256, 256>>>(W);
    fused_kernel<<<512, 320, FUSED_SMEM>>>(x, theta, y);
}

// round 10
// speedup vs baseline: 1.3562x; 1.1329x over previous
#include <cuda_runtime.h>
#include <cstdint>

#define S_DIM 8192
#define E_DIM 512
#define B_DIM 8
#define SE_DIM (S_DIM * E_DIM)
#define M_TOTAL 65536
#define K_DIM 512
#define N_DIM 512

#if defined(__CUDA_ARCH_FEAT_SM103_ALL) || defined(__CUDA_ARCH_FEAT_SM100_ALL) || \
    defined(__CUDA_ARCH_FEAT_SM101_ALL) || defined(__CUDA_ARCH_FEAT_SM110_ALL)
#define HAS_TCGEN05 1
#else
#define HAS_TCGEN05 0
#endif

// W scratch, CHUNK-MAJOR + PRE-SWIZZLED:
//   g_W32 byte (c*65536 + sw128(n*128 + j*4)) = tf32(W[n][c*32 + j])
__device__ float g_W32[(size_t)N_DIM * K_DIM];

// ---------------------------------------------------------------------------
__device__ __forceinline__ float to_tf32(float v) {
    float r;
    asm("cvt.rna.tf32.f32 %0, %1;" : "=f"(r) : "f"(v));
    return r;
}

// XU-free cos + tf32 rounding (fma/alu pipes only). Valid for |t| < ~1e5.
__device__ __forceinline__ uint32_t cos_tf32_bits(float t) {
    const float MAGIC = 12582912.0f;               // 1.5 * 2^23
    float g = fmaf(t, 0.63661977236758134f, MAGIC);
    int q = __float_as_int(g);
    float qf = g - MAGIC;
    float r = fmaf(qf, -1.57079637050628662109375f, t);
    r = fmaf(qf, 4.37113900018624283e-8f, r);
    float z = r * r;
    float sp = fmaf(z, -1.9515295891e-4f, 8.3321608736e-3f);
    sp = fmaf(z, sp, -1.6666654611e-1f);
    float sinr = fmaf(r * z, sp, r);
    float cp = fmaf(z, 2.443315711809948e-5f, -1.388731625493765e-3f);
    cp = fmaf(z, cp, 4.166664568298827e-2f);
    cp = fmaf(z, cp, -0.5f);
    float cosr = fmaf(z, cp, 1.0f);
    uint32_t res = (q & 1) ? __float_as_uint(sinr) : __float_as_uint(cosr);
    res ^= (uint32_t)((q + 1) & 2) << 30;
    res = (res + 0x1000u) & 0xFFFFE000u;           // tf32 rna
    return res;
}

__device__ __forceinline__ uint32_t smem_u32(const void* p) {
    uint32_t a;
    asm("{ .reg .u64 t; cvta.to.shared.u64 t, %1; cvt.u32.u64 %0, t; }" : "=r"(a) : "l"(p));
    return a;
}

#define MBAR_INIT(addr, cnt) \
    asm volatile("mbarrier.init.shared.b64 [%0], %1;" :: "r"(addr), "r"(cnt) : "memory")

#define MBAR_WAIT(addr, par) do {                                               \
    uint32_t _m = (addr); uint32_t _p = (par); uint32_t _d;                     \
    asm volatile("{\n\t.reg .pred p;\n\t"                                       \
        "mbarrier.try_wait.parity.acquire.cta.shared::cta.b64 p, [%1], %2;\n\t" \
        "selp.b32 %0, 1, 0, p;\n\t}"                                            \
        : "=r"(_d) : "r"(_m), "r"(_p) : "memory");                              \
    if (!_d) {                                                                  \
        asm volatile("{\n\t.reg .pred P1;\n\t"                                  \
            "WL_%=:\n\t"                                                        \
            "mbarrier.try_wait.parity.acquire.cta.shared::cta.b64 P1, [%0], %1, 0x989680;\n\t" \
            "@P1 bra.uni WD_%=;\n\t"                                            \
            "bra.uni WL_%=;\n\t"                                                \
            "WD_%=:\n\t}" :: "r"(_m), "r"(_p) : "memory");                      \
    }                                                                           \
} while (0)

__device__ __forceinline__ uint64_t make_desc_sw128(uint32_t addr) {
    const uint64_t base = (uint64_t(2) << 61) | (uint64_t(1) << 46) |
                          (uint64_t(64) << 32) | (uint64_t(1) << 16);
    return base | ((uint64_t)(addr >> 4) & 0x3FFF);
}

#define STS128(addr, a0, a1, a2, a3) \
    asm volatile("st.shared.v4.b32 [%0], {%1, %2, %3, %4};" \
                 :: "r"(addr), "r"(a0), "r"(a1), "r"(a2), "r"(a3) : "memory")

#if HAS_TCGEN05
__device__ __forceinline__ void mma_tf32_ss(uint32_t d_tmem, uint64_t a_desc,
                                            uint64_t b_desc, uint32_t idesc,
                                            uint32_t enable) {
    asm volatile(
        "{\n\t.reg .pred p;\n\t"
        "setp.ne.u32 p, %4, 0;\n\t"
        "tcgen05.mma.cta_group::1.kind::tf32 [%0], %1, %2, %3, p;\n\t}"
        :: "r"(d_tmem), "l"(a_desc), "l"(b_desc), "r"(idesc), "r"(enable)
        : "memory");
}
#endif

// ---------------------------------------------------------------------------
// Stage 0: round W to tf32, chunk-major + pre-swizzled.
// ---------------------------------------------------------------------------
__global__ __launch_bounds__(256) void roundw_kernel(const float* __restrict__ W) {
    int tid = blockIdx.x * 256 + threadIdx.x;
    int n    = tid >> 7;
    int rest = tid & 127;
    int c    = rest >> 3;
    int seg  = rest & 7;

    float4 v = *(const float4*)(W + (size_t)n * K_DIM + c * 32 + seg * 4);
    v.x = to_tf32(v.x); v.y = to_tf32(v.y); v.z = to_tf32(v.z); v.w = to_tf32(v.w);

    uint32_t byte_off = (uint32_t)n * 128 + seg * 16;
    uint32_t sw = byte_off ^ ((byte_off >> 3) & 0x70);
    *(float4*)((char*)g_W32 + (size_t)c * 65536 + sw) = v;
}

// ---------------------------------------------------------------------------
// Fused kernel, COALESCED-x tiling.
// Tile t: b = t>>6, g = t&63, q0 = 2g. A-tile row a (0..127) = output row
// (b, h*128 + q) with h = a>>1, q = q0 + (a&1):
//   A[a][k] = tf32cos(x[b, 64q + k/8, 8h + k%8] + theta[k%8])
// Chunk i needs x rows {64(q0+dq) + 4i + j} — 8 FULL contiguous rows,
// loaded perfectly coalesced (warp w = (dq,j) owns one row; lane l loads
// 16B units l, l+32, l+64, l+96 → nL=4 per LDG).
//   warps 0-7 : x load + cos + A STS (4-stage ring) + epilogue
//   warp 8    : MMA issue, commits doneA + doneB per chunk
//   warp 9    : B bulk-copy producer (2-stage ring)
// ---------------------------------------------------------------------------
#define NCHUNK 16
#define NSA 4
#define NSB 2
#define SMEM_A0 1024
#define A_STAGE 16384
#define SMEM_B0 (SMEM_A0 + NSA * A_STAGE)     // 66560
#define B_STAGE 65536
#define FUSED_SMEM (SMEM_B0 + NSB * B_STAGE)  // 197632

#define OFF_FULLA 16
#define OFF_DONEA 48
#define OFF_FULLB 80
#define OFF_DONEB 96

static constexpr uint32_t IDESC_N256 =
    (1u << 4)                // D = F32
    | (2u << 7)              // A = TF32
    | (2u << 10)             // B = TF32
    | ((256u / 8u) << 17)    // N = 256
    | ((128u / 16u) << 24);  // M = 128

extern "C" __global__ void __launch_bounds__(320, 1)
fused_kernel(const float* __restrict__ x, const float* __restrict__ theta,
             float* __restrict__ C) {
#if HAS_TCGEN05
    extern __shared__ char smem[];
    uint32_t smem_base = smem_u32(smem);
    int tid = threadIdx.x;
    int wid = tid >> 5;
    int lid = tid & 31;

    int t = blockIdx.x;
    int b = t >> 6;
    int g = t & 63;
    int q0 = g << 1;

    uint32_t fullA = smem_base + OFF_FULLA;
    uint32_t doneA = smem_base + OFF_DONEA;
    uint32_t fullB = smem_base + OFF_FULLB;
    uint32_t doneB = smem_base + OFF_DONEB;

    if (tid == 0) {
        for (int s = 0; s < NSA; s++) {
            MBAR_INIT(fullA + 8 * s, 8);     // one arrive per worker warp
            MBAR_INIT(doneA + 8 * s, 1);
        }
        for (int s = 0; s < NSB; s++) {
            MBAR_INIT(fullB + 8 * s, 1);
            MBAR_INIT(doneB + 8 * s, 1);
        }
    }
    if (wid == 8) {
        asm volatile("tcgen05.alloc.cta_group::1.sync.aligned.shared::cta.b32 [%0], %1;"
                     :: "r"(smem_base), "r"(512u) : "memory");
        asm volatile("tcgen05.relinquish_alloc_permit.cta_group::1.sync.aligned;");
    }
    __syncthreads();
    uint32_t tmem;
    asm volatile("ld.shared.b32 %0, [%1];" : "=r"(tmem) : "r"(smem_base));

    if (wid < 8) {
        // ================= worker warps (256 threads) =================
        int dq = wid >> 2;          // 0..1
        int j  = wid & 3;           // 0..3
        int wh = lid & 1;           // theta half (fixed per thread)
        float tha = __ldg(theta + wh * 4 + 0);
        float thb = __ldg(theta + wh * 4 + 1);
        float thc = __ldg(theta + wh * 4 + 2);
        float thd = __ldg(theta + wh * 4 + 3);

        // base of this warp's x rows: s = 64*(q0+dq) + 4i + j
        const float* xrow0 = x + ((size_t)b << 22) +
                             (size_t)(64 * (q0 + dq) + j) * E_DIM;

        // A rows this thread writes (per u): a_u = ((lid + 32u) & ~1) + dq
        // STS byte offset within row-chunk: (j*32 + wh*16) ^ ((a&7)*16)
        uint32_t koff = (uint32_t)(j * 32 + wh * 16);

        for (int i = 0; i < NCHUNK; i++) {
            // coalesced x loads for this chunk, issued before the ring wait
            const float* xp = xrow0 + (size_t)(4 * i) * E_DIM + lid * 4;
            float4 x0 = *(const float4*)(xp);
            float4 x1 = *(const float4*)(xp + 128);
            float4 x2 = *(const float4*)(xp + 256);
            float4 x3 = *(const float4*)(xp + 384);

            int st = i & 3;
            if (i >= NSA) MBAR_WAIT(doneA + 8 * st, ((i - NSA) >> 2) & 1);

            uint32_t ast = smem_base + SMEM_A0 + st * A_STAGE;
#pragma unroll
            for (int u = 0; u < 4; u++) {
                float4 xv = (u == 0) ? x0 : (u == 1) ? x1 : (u == 2) ? x2 : x3;
                uint32_t v0 = cos_tf32_bits(xv.x + tha);
                uint32_t v1 = cos_tf32_bits(xv.y + thb);
                uint32_t v2 = cos_tf32_bits(xv.z + thc);
                uint32_t v3 = cos_tf32_bits(xv.w + thd);
                int a = ((lid + 32 * u) & ~1) + dq;
                uint32_t addr = ast + (uint32_t)a * 128 +
                                (koff ^ (uint32_t)((a & 7) * 16));
                STS128(addr, v0, v1, v2, v3);
            }

            asm volatile("fence.proxy.async.shared::cta;" ::: "memory");
            __syncwarp();
            if (lid == 0)
                asm volatile("mbarrier.arrive.shared.b64 _, [%0];"
                             :: "r"(fullA + 8 * st) : "memory");
        }

        // ================= epilogue =================
        MBAR_WAIT(doneA + 8 * 3, 1);    // 4th fire of stage-3 ring
        asm volatile("tcgen05.fence::after_thread_sync;" ::: "memory");

        int row = (wid & 3) * 32 + lid;      // A-tile row a
        int c0 = (wid >= 4) ? 256 : 0;
        int crow = (b << 13) + ((row >> 1) << 7) + q0 + (row & 1);
        float* Crow = C + (size_t)crow * N_DIM + c0;
#pragma unroll
        for (int c = 0; c < 8; c++) {
            uint32_t d[32];
            asm volatile(
                "tcgen05.ld.sync.aligned.32x32b.x32.b32 "
                "{%0, %1, %2, %3, %4, %5, %6, %7, "
                " %8, %9, %10, %11, %12, %13, %14, %15, "
                " %16, %17, %18, %19, %20, %21, %22, %23, "
                " %24, %25, %26, %27, %28, %29, %30, %31}, [%32];"
                : "=r"(d[0]), "=r"(d[1]), "=r"(d[2]), "=r"(d[3]),
                  "=r"(d[4]), "=r"(d[5]), "=r"(d[6]), "=r"(d[7]),
                  "=r"(d[8]), "=r"(d[9]), "=r"(d[10]), "=r"(d[11]),
                  "=r"(d[12]), "=r"(d[13]), "=r"(d[14]), "=r"(d[15]),
                  "=r"(d[16]), "=r"(d[17]), "=r"(d[18]), "=r"(d[19]),
                  "=r"(d[20]), "=r"(d[21]), "=r"(d[22]), "=r"(d[23]),
                  "=r"(d[24]), "=r"(d[25]), "=r"(d[26]), "=r"(d[27]),
                  "=r"(d[28]), "=r"(d[29]), "=r"(d[30]), "=r"(d[31])
                : "r"(tmem + c0 + 32 * c));
            asm volatile("tcgen05.wait::ld.sync.aligned;" ::: "memory");
#pragma unroll
            for (int jj = 0; jj < 8; jj++) {
                float4 o = make_float4(__uint_as_float(d[4 * jj + 0]),
                                       __uint_as_float(d[4 * jj + 1]),
                                       __uint_as_float(d[4 * jj + 2]),
                                       __uint_as_float(d[4 * jj + 3]));
                *(float4*)(Crow + 32 * c + 4 * jj) = o;
            }
        }
        asm volatile("tcgen05.fence::before_thread_sync;" ::: "memory");
    } else if (wid == 8) {
        // ================= MMA warp =================
        for (int i = 0; i < NCHUNK; i++) {
            int stA = i & 3;
            int stB = i & 1;
            MBAR_WAIT(fullA + 8 * stA, (i >> 2) & 1);
            MBAR_WAIT(fullB + 8 * stB, (i >> 1) & 1);
            asm volatile("fence.proxy.async.shared::cta;" ::: "memory");
            if (lid == 0) {
                uint32_t ab = smem_base + SMEM_A0 + stA * A_STAGE;
                uint32_t bb = smem_base + SMEM_B0 + stB * B_STAGE;
                uint64_t ad  = make_desc_sw128(ab);
                uint64_t bd0 = make_desc_sw128(bb);
                uint64_t bd1 = make_desc_sw128(bb + 256 * 128);
#pragma unroll
                for (int k = 0; k < 4; k++) {
                    uint32_t en = (i | k) != 0;
                    mma_tf32_ss(tmem,       ad + 2 * k, bd0 + 2 * k, IDESC_N256, en);
                    mma_tf32_ss(tmem + 256, ad + 2 * k, bd1 + 2 * k, IDESC_N256, en);
                }
                asm volatile(
                    "tcgen05.commit.cta_group::1.mbarrier::arrive::one.shared::cluster.b64 [%0];"
                    :: "r"(doneA + 8 * stA) : "memory");
                asm volatile(
                    "tcgen05.commit.cta_group::1.mbarrier::arrive::one.shared::cluster.b64 [%0];"
                    :: "r"(doneB + 8 * stB) : "memory");
            }
        }
    } else {
        // ================= B producer warp (wid == 9) =================
        for (int i = 0; i < NCHUNK; i++) {
            int stB = i & 1;
            if (i >= NSB) MBAR_WAIT(doneB + 8 * stB, ((i - NSB) >> 1) & 1);
            if (lid == 0) {
                uint32_t bar = fullB + 8 * stB;
                asm volatile("mbarrier.arrive.expect_tx.shared::cta.b64 _, [%0], %1;"
                             :: "r"(bar), "r"((uint32_t)B_STAGE) : "memory");
                const char* src = (const char*)g_W32 + (size_t)i * B_STAGE;
                uint32_t dst = smem_base + SMEM_B0 + stB * B_STAGE;
                asm volatile(
                    "cp.async.bulk.shared::cta.global.mbarrier::complete_tx::bytes "
                    "[%0], [%1], %2, [%3];"
                    :: "r"(dst), "l"(src), "r"((uint32_t)B_STAGE), "r"(bar)
                    : "memory");
            }
        }
    }

    __syncthreads();
    if (wid == 8) {
        asm volatile("tcgen05.dealloc.cta_group::1.sync.aligned.b32 %0, %1;"
                     :: "r"(tmem), "r"(512u));
    }
#else
    // Correct SIMT fallback for the non-arch-specific cubin (never selected
    // on GB300). Same math + row mapping as the tensor path.
    int t = blockIdx.x;
    int b = t >> 6;
    int q0 = (t & 63) << 1;
    for (int idx = threadIdx.x; idx < 128 * N_DIM; idx += 320) {
        int a = idx >> 9, n = idx & 511;
        int h = a >> 1;
        int q = q0 + (a & 1);
        float acc = 0.0f;
        for (int k = 0; k < K_DIM; k++) {
            int sl = k >> 3, w = k & 7;
            float xv = x[(size_t)b * SE_DIM + (size_t)(64 * q + sl) * E_DIM + 8 * h + w];
            float av = __uint_as_float(cos_tf32_bits(xv + theta[w]));
            int c = k >> 5, kk = k & 31;
            uint32_t byte_off = (uint32_t)n * 128 + kk * 4;
            uint32_t sw = byte_off ^ ((byte_off >> 3) & 0x70);
            float wv = *(const float*)((const char*)g_W32 + (size_t)c * 65536 + sw);
            acc = fmaf(av, wv, acc);
        }
        C[(size_t)((b << 13) + (h << 7) + q) * N_DIM + n] = acc;
    }
#endif
}

// ---------------------------------------------------------------------------
extern "C" void kernel_launch(void* const* d_in, const int* in_sizes, int n_in,
                              void* d_out, int out_size) {
    const float* x     = (const float*)d_in[0];
    const float* theta = (const float*)d_in[1];
    const float* W     = (const float*)d_in[2];
    float* y = (float*)d_out;

    static bool attr_done = false;
    if (!attr_done) {
        cudaFuncSetAttribute(fused_kernel,
                             cudaFuncAttributeMaxDynamicSharedMemorySize, FUSED_SMEM);
        attr_done = true;
    }

    roundw_kernel<<<256, 256>>>(W);
    fused_kernel<<<512, 320, FUSED_SMEM>>>(x, theta, y);
}